// round 2
// baseline (speedup 1.0000x reference)
#include <cuda_runtime.h>
#include <math.h>

#define T_ 2048
#define H_ 2048
#define F_ 1408
#define E_ 60
#define TOPK_ 4
#define SF_ 5632

// ---- device scratch (no allocations allowed) ----
__device__ float g_S[(size_t)T_ * SF_];            // shared-expert intermediate [T, SF]  (46 MB)
__device__ float g_Hbuf[(size_t)T_ * TOPK_ * F_];  // expert intermediate per pair [8192, F] (46 MB)
__device__ int   g_cnt[E_];
__device__ int   g_base[E_];
__device__ int   g_tok[E_ * T_];
__device__ float g_wt[E_ * T_];
__device__ float g_gate[T_];

__device__ __forceinline__ float siluf(float v) { return v / (1.f + expf(-v)); }

// ============================ init / scan ============================
__global__ void init_kernel() {
    int i = threadIdx.x;
    if (i < E_) g_cnt[i] = 0;
}

__global__ void scan_kernel() {
    if (threadIdx.x == 0) {
        int s = 0;
        for (int e = 0; e < E_; ++e) { g_base[e] = s; s += g_cnt[e]; }
    }
}

// ============================ router ============================
// One block per token: logits = x @ router_w, softmax, top-4 -> expert lists.
// Also computes sigmoid(x @ sh_expert_gate).
__global__ __launch_bounds__(256) void router_kernel(
    const float* __restrict__ X, const float* __restrict__ RW,
    const float* __restrict__ SEG)
{
    int t = blockIdx.x;
    __shared__ float xs[H_];
    __shared__ float part[64][4];
    __shared__ float logits[E_];
    __shared__ float red[256];
    int tid = threadIdx.x;

    for (int i = tid; i < H_; i += 256) xs[i] = X[(size_t)t * H_ + i];
    __syncthreads();

    int e = tid >> 2, q = tid & 3;
    if (e < E_) {
        float s = 0.f;
        int h0 = q * (H_ / 4);
        for (int h = h0; h < h0 + H_ / 4; ++h) s += xs[h] * RW[(size_t)h * E_ + e];
        part[e][q] = s;
    }
    float gsum = 0.f;
    for (int i = tid; i < H_; i += 256) gsum += xs[i] * SEG[i];
    red[tid] = gsum;
    __syncthreads();

    if (e < E_ && q == 0)
        logits[e] = part[e][0] + part[e][1] + part[e][2] + part[e][3];

    for (int st = 128; st > 0; st >>= 1) {
        if (tid < st) red[tid] += red[tid + st];
        __syncthreads();
    }

    if (tid == 0) {
        g_gate[t] = 1.f / (1.f + expf(-red[0]));
        float mx = -1e30f;
        for (int i = 0; i < E_; ++i) mx = fmaxf(mx, logits[i]);
        float sum = 0.f;
        for (int i = 0; i < E_; ++i) { logits[i] = expf(logits[i] - mx); sum += logits[i]; }
        float inv = 1.f / sum;
        for (int k = 0; k < TOPK_; ++k) {
            int bi = 0; float bv = -1.f;
            for (int i = 0; i < E_; ++i)
                if (logits[i] > bv) { bv = logits[i]; bi = i; }
            logits[bi] = -1.f;
            int slot = atomicAdd(&g_cnt[bi], 1);
            g_tok[bi * T_ + slot] = t;
            g_wt[bi * T_ + slot]  = bv * inv;
        }
    }
}

// ============================ shared-expert up/gate ============================
// g_S = silu(X @ Gw) * (X @ Uw).  BM=128 BN=64 TK=16, micro 8x4, dual accumulators.
__global__ __launch_bounds__(256) void shared_upgate_kernel(
    const float* __restrict__ X, const float* __restrict__ Gw,
    const float* __restrict__ Uw)
{
    const int n0 = blockIdx.x * 64;
    const int m0 = blockIdx.y * 128;
    __shared__ float As[2][16][132];
    __shared__ float Bg[2][16][64];
    __shared__ float Bu[2][16][64];
    const int tid = threadIdx.x;
    const int tx = tid & 15;
    const int ty = tid >> 4;
    const int am0 = tid >> 2, akq = (tid & 3) * 4;
    const int bkr = tid >> 4, bnq = (tid & 15) * 4;

    float cg[8][4], cu[8][4];
    #pragma unroll
    for (int i = 0; i < 8; ++i)
        #pragma unroll
        for (int j = 0; j < 4; ++j) { cg[i][j] = 0.f; cu[i][j] = 0.f; }

    const int KT = H_ / 16;
    {
        float4 v = *(const float4*)&X[(size_t)(m0 + am0) * H_ + akq];
        As[0][akq + 0][am0] = v.x; As[0][akq + 1][am0] = v.y;
        As[0][akq + 2][am0] = v.z; As[0][akq + 3][am0] = v.w;
        v = *(const float4*)&X[(size_t)(m0 + am0 + 64) * H_ + akq];
        As[0][akq + 0][am0 + 64] = v.x; As[0][akq + 1][am0 + 64] = v.y;
        As[0][akq + 2][am0 + 64] = v.z; As[0][akq + 3][am0 + 64] = v.w;
        *(float4*)&Bg[0][bkr][bnq] = *(const float4*)&Gw[(size_t)bkr * SF_ + n0 + bnq];
        *(float4*)&Bu[0][bkr][bnq] = *(const float4*)&Uw[(size_t)bkr * SF_ + n0 + bnq];
    }
    __syncthreads();

    float4 ra0, ra1, rbg, rbu;
    for (int kt = 0; kt < KT; ++kt) {
        int cur = kt & 1;
        if (kt + 1 < KT) {
            int k0 = (kt + 1) * 16;
            ra0 = *(const float4*)&X[(size_t)(m0 + am0) * H_ + k0 + akq];
            ra1 = *(const float4*)&X[(size_t)(m0 + am0 + 64) * H_ + k0 + akq];
            rbg = *(const float4*)&Gw[(size_t)(k0 + bkr) * SF_ + n0 + bnq];
            rbu = *(const float4*)&Uw[(size_t)(k0 + bkr) * SF_ + n0 + bnq];
        }
        #pragma unroll 4
        for (int k = 0; k < 16; ++k) {
            float4 a0 = *(const float4*)&As[cur][k][ty * 8];
            float4 a1 = *(const float4*)&As[cur][k][ty * 8 + 4];
            float4 bg = *(const float4*)&Bg[cur][k][tx * 4];
            float4 bu = *(const float4*)&Bu[cur][k][tx * 4];
            float a[8] = {a0.x, a0.y, a0.z, a0.w, a1.x, a1.y, a1.z, a1.w};
            float gg[4] = {bg.x, bg.y, bg.z, bg.w};
            float uu[4] = {bu.x, bu.y, bu.z, bu.w};
            #pragma unroll
            for (int i = 0; i < 8; ++i)
                #pragma unroll
                for (int j = 0; j < 4; ++j) {
                    cg[i][j] += a[i] * gg[j];
                    cu[i][j] += a[i] * uu[j];
                }
        }
        if (kt + 1 < KT) {
            int nb = (kt + 1) & 1;
            As[nb][akq + 0][am0] = ra0.x; As[nb][akq + 1][am0] = ra0.y;
            As[nb][akq + 2][am0] = ra0.z; As[nb][akq + 3][am0] = ra0.w;
            As[nb][akq + 0][am0 + 64] = ra1.x; As[nb][akq + 1][am0 + 64] = ra1.y;
            As[nb][akq + 2][am0 + 64] = ra1.z; As[nb][akq + 3][am0 + 64] = ra1.w;
            *(float4*)&Bg[nb][bkr][bnq] = rbg;
            *(float4*)&Bu[nb][bkr][bnq] = rbu;
        }
        __syncthreads();
    }

    #pragma unroll
    for (int i = 0; i < 8; ++i) {
        int row = m0 + ty * 8 + i;
        float4 o;
        o.x = siluf(cg[i][0]) * cu[i][0];
        o.y = siluf(cg[i][1]) * cu[i][1];
        o.z = siluf(cg[i][2]) * cu[i][2];
        o.w = siluf(cg[i][3]) * cu[i][3];
        *(float4*)&g_S[(size_t)row * SF_ + n0 + tx * 4] = o;
    }
}

// ============================ shared-expert down ============================
// out = sigmoid_gate[t] * (g_S @ Wd).  BM=128 BN=128 TK=8, micro 8x8.
__global__ __launch_bounds__(256) void shared_down_kernel(
    const float* __restrict__ Wd, float* __restrict__ Out)
{
    const int n0 = blockIdx.x * 128;
    const int m0 = blockIdx.y * 128;
    __shared__ float As[2][8][132];
    __shared__ float Bs[2][8][128];
    const int tid = threadIdx.x;
    const int tx = tid & 15;
    const int ty = tid >> 4;
    const int am0 = tid >> 1, akq = (tid & 1) * 4;
    const int bkr = tid >> 5, bnq = (tid & 31) * 4;

    float acc[8][8];
    #pragma unroll
    for (int i = 0; i < 8; ++i)
        #pragma unroll
        for (int j = 0; j < 8; ++j) acc[i][j] = 0.f;

    const int KT = SF_ / 8;
    {
        float4 v = *(const float4*)&g_S[(size_t)(m0 + am0) * SF_ + akq];
        As[0][akq + 0][am0] = v.x; As[0][akq + 1][am0] = v.y;
        As[0][akq + 2][am0] = v.z; As[0][akq + 3][am0] = v.w;
        *(float4*)&Bs[0][bkr][bnq] = *(const float4*)&Wd[(size_t)bkr * H_ + n0 + bnq];
    }
    __syncthreads();

    float4 ra, rb;
    for (int kt = 0; kt < KT; ++kt) {
        int cur = kt & 1;
        if (kt + 1 < KT) {
            int k0 = (kt + 1) * 8;
            ra = *(const float4*)&g_S[(size_t)(m0 + am0) * SF_ + k0 + akq];
            rb = *(const float4*)&Wd[(size_t)(k0 + bkr) * H_ + n0 + bnq];
        }
        #pragma unroll
        for (int k = 0; k < 8; ++k) {
            float4 a0 = *(const float4*)&As[cur][k][ty * 8];
            float4 a1 = *(const float4*)&As[cur][k][ty * 8 + 4];
            float4 b0 = *(const float4*)&Bs[cur][k][tx * 8];
            float4 b1 = *(const float4*)&Bs[cur][k][tx * 8 + 4];
            float a[8] = {a0.x, a0.y, a0.z, a0.w, a1.x, a1.y, a1.z, a1.w};
            float b[8] = {b0.x, b0.y, b0.z, b0.w, b1.x, b1.y, b1.z, b1.w};
            #pragma unroll
            for (int i = 0; i < 8; ++i)
                #pragma unroll
                for (int j = 0; j < 8; ++j) acc[i][j] += a[i] * b[j];
        }
        if (kt + 1 < KT) {
            int nb = (kt + 1) & 1;
            As[nb][akq + 0][am0] = ra.x; As[nb][akq + 1][am0] = ra.y;
            As[nb][akq + 2][am0] = ra.z; As[nb][akq + 3][am0] = ra.w;
            *(float4*)&Bs[nb][bkr][bnq] = rb;
        }
        __syncthreads();
    }

    #pragma unroll
    for (int i = 0; i < 8; ++i) {
        int row = m0 + ty * 8 + i;
        float gt = g_gate[row];
        float4 o0, o1;
        o0.x = gt * acc[i][0]; o0.y = gt * acc[i][1]; o0.z = gt * acc[i][2]; o0.w = gt * acc[i][3];
        o1.x = gt * acc[i][4]; o1.y = gt * acc[i][5]; o1.z = gt * acc[i][6]; o1.w = gt * acc[i][7];
        *(float4*)&Out[(size_t)row * H_ + n0 + tx * 8]     = o0;
        *(float4*)&Out[(size_t)row * H_ + n0 + tx * 8 + 4] = o1;
    }
}

// ============================ expert up/gate (grouped, gather) ============================
// For expert e: Hbuf[pair] = silu(x[tok] @ Wg_e) * (x[tok] @ Wu_e).
// BM=64 BN=128 TK=16, micro 4x8, dual accumulators.
__global__ __launch_bounds__(256) void expert_upgate_kernel(
    const float* __restrict__ X, const float* __restrict__ WG,
    const float* __restrict__ WU)
{
    const int e = blockIdx.z;
    const int cnt = g_cnt[e];
    const int m0 = blockIdx.y * 64;
    if (m0 >= cnt) return;
    const int n0 = blockIdx.x * 128;

    __shared__ int toks[64];
    __shared__ float As[2][16][68];
    __shared__ float Bg[2][16][128];
    __shared__ float Bu[2][16][128];
    const int tid = threadIdx.x;
    const int tx = tid & 15;
    const int ty = tid >> 4;
    const int am0 = tid >> 2, akq = (tid & 3) * 4;

    if (tid < 64) {
        int mm = m0 + tid;
        toks[tid] = g_tok[e * T_ + (mm < cnt ? mm : cnt - 1)];
    }
    __syncthreads();

    const float* Gp = WG + (size_t)e * H_ * F_;
    const float* Up = WU + (size_t)e * H_ * F_;

    float cg[4][8], cu[4][8];
    #pragma unroll
    for (int i = 0; i < 4; ++i)
        #pragma unroll
        for (int j = 0; j < 8; ++j) { cg[i][j] = 0.f; cu[i][j] = 0.f; }

    const int KT = H_ / 16;
    {
        float4 v = *(const float4*)&X[(size_t)toks[am0] * H_ + akq];
        As[0][akq + 0][am0] = v.x; As[0][akq + 1][am0] = v.y;
        As[0][akq + 2][am0] = v.z; As[0][akq + 3][am0] = v.w;
        #pragma unroll
        for (int l = 0; l < 2; ++l) {
            int idx = tid + l * 256;
            int kr = idx >> 5, nq = (idx & 31) * 4;
            *(float4*)&Bg[0][kr][nq] = *(const float4*)&Gp[(size_t)kr * F_ + n0 + nq];
            *(float4*)&Bu[0][kr][nq] = *(const float4*)&Up[(size_t)kr * F_ + n0 + nq];
        }
    }
    __syncthreads();

    float4 ra, rbg0, rbg1, rbu0, rbu1;
    for (int kt = 0; kt < KT; ++kt) {
        int cur = kt & 1;
        if (kt + 1 < KT) {
            int k0 = (kt + 1) * 16;
            ra = *(const float4*)&X[(size_t)toks[am0] * H_ + k0 + akq];
            int kr0 = tid >> 5, nq0 = (tid & 31) * 4;
            int idx1 = tid + 256;
            int kr1 = idx1 >> 5, nq1 = (idx1 & 31) * 4;
            rbg0 = *(const float4*)&Gp[(size_t)(k0 + kr0) * F_ + n0 + nq0];
            rbg1 = *(const float4*)&Gp[(size_t)(k0 + kr1) * F_ + n0 + nq1];
            rbu0 = *(const float4*)&Up[(size_t)(k0 + kr0) * F_ + n0 + nq0];
            rbu1 = *(const float4*)&Up[(size_t)(k0 + kr1) * F_ + n0 + nq1];
        }
        #pragma unroll 4
        for (int k = 0; k < 16; ++k) {
            float4 av = *(const float4*)&As[cur][k][ty * 4];
            float4 bg0 = *(const float4*)&Bg[cur][k][tx * 8];
            float4 bg1 = *(const float4*)&Bg[cur][k][tx * 8 + 4];
            float4 bu0 = *(const float4*)&Bu[cur][k][tx * 8];
            float4 bu1 = *(const float4*)&Bu[cur][k][tx * 8 + 4];
            float a[4] = {av.x, av.y, av.z, av.w};
            float gg[8] = {bg0.x, bg0.y, bg0.z, bg0.w, bg1.x, bg1.y, bg1.z, bg1.w};
            float uu[8] = {bu0.x, bu0.y, bu0.z, bu0.w, bu1.x, bu1.y, bu1.z, bu1.w};
            #pragma unroll
            for (int i = 0; i < 4; ++i)
                #pragma unroll
                for (int j = 0; j < 8; ++j) {
                    cg[i][j] += a[i] * gg[j];
                    cu[i][j] += a[i] * uu[j];
                }
        }
        if (kt + 1 < KT) {
            int nb = (kt + 1) & 1;
            As[nb][akq + 0][am0] = ra.x; As[nb][akq + 1][am0] = ra.y;
            As[nb][akq + 2][am0] = ra.z; As[nb][akq + 3][am0] = ra.w;
            int kr0 = tid >> 5, nq0 = (tid & 31) * 4;
            int idx1 = tid + 256;
            int kr1 = idx1 >> 5, nq1 = (idx1 & 31) * 4;
            *(float4*)&Bg[nb][kr0][nq0] = rbg0;
            *(float4*)&Bg[nb][kr1][nq1] = rbg1;
            *(float4*)&Bu[nb][kr0][nq0] = rbu0;
            *(float4*)&Bu[nb][kr1][nq1] = rbu1;
        }
        __syncthreads();
    }

    const int pbase = g_base[e];
    #pragma unroll
    for (int i = 0; i < 4; ++i) {
        int row = m0 + ty * 4 + i;
        if (row < cnt) {
            size_t pr = (size_t)(pbase + row) * F_;
            float4 o0, o1;
            o0.x = siluf(cg[i][0]) * cu[i][0]; o0.y = siluf(cg[i][1]) * cu[i][1];
            o0.z = siluf(cg[i][2]) * cu[i][2]; o0.w = siluf(cg[i][3]) * cu[i][3];
            o1.x = siluf(cg[i][4]) * cu[i][4]; o1.y = siluf(cg[i][5]) * cu[i][5];
            o1.z = siluf(cg[i][6]) * cu[i][6]; o1.w = siluf(cg[i][7]) * cu[i][7];
            *(float4*)&g_Hbuf[pr + n0 + tx * 8]     = o0;
            *(float4*)&g_Hbuf[pr + n0 + tx * 8 + 4] = o1;
        }
    }
}

// ============================ expert down (grouped, scatter-add) ============================
// out[tok] += w * (Hbuf_pair @ Wd_e).  BM=64 BN=128 TK=16, micro 4x8.
__global__ __launch_bounds__(256) void expert_down_kernel(
    const float* __restrict__ WD, float* __restrict__ Out)
{
    const int e = blockIdx.z;
    const int cnt = g_cnt[e];
    const int m0 = blockIdx.y * 64;
    if (m0 >= cnt) return;
    const int n0 = blockIdx.x * 128;
    const int pbase = g_base[e];

    __shared__ float As[2][16][68];
    __shared__ float Bs[2][16][128];
    const int tid = threadIdx.x;
    const int tx = tid & 15;
    const int ty = tid >> 4;
    const int am0 = tid >> 2, akq = (tid & 3) * 4;
    const int arow = pbase + (m0 + am0 < cnt ? m0 + am0 : cnt - 1);

    const float* Dp = WD + (size_t)e * F_ * H_;

    float acc[4][8];
    #pragma unroll
    for (int i = 0; i < 4; ++i)
        #pragma unroll
        for (int j = 0; j < 8; ++j) acc[i][j] = 0.f;

    const int KT = F_ / 16;
    {
        float4 v = *(const float4*)&g_Hbuf[(size_t)arow * F_ + akq];
        As[0][akq + 0][am0] = v.x; As[0][akq + 1][am0] = v.y;
        As[0][akq + 2][am0] = v.z; As[0][akq + 3][am0] = v.w;
        #pragma unroll
        for (int l = 0; l < 2; ++l) {
            int idx = tid + l * 256;
            int kr = idx >> 5, nq = (idx & 31) * 4;
            *(float4*)&Bs[0][kr][nq] = *(const float4*)&Dp[(size_t)kr * H_ + n0 + nq];
        }
    }
    __syncthreads();

    float4 ra, rb0, rb1;
    for (int kt = 0; kt < KT; ++kt) {
        int cur = kt & 1;
        if (kt + 1 < KT) {
            int k0 = (kt + 1) * 16;
            ra = *(const float4*)&g_Hbuf[(size_t)arow * F_ + k0 + akq];
            int kr0 = tid >> 5, nq0 = (tid & 31) * 4;
            int idx1 = tid + 256;
            int kr1 = idx1 >> 5, nq1 = (idx1 & 31) * 4;
            rb0 = *(const float4*)&Dp[(size_t)(k0 + kr0) * H_ + n0 + nq0];
            rb1 = *(const float4*)&Dp[(size_t)(k0 + kr1) * H_ + n0 + nq1];
        }
        #pragma unroll 4
        for (int k = 0; k < 16; ++k) {
            float4 av = *(const float4*)&As[cur][k][ty * 4];
            float4 b0 = *(const float4*)&Bs[cur][k][tx * 8];
            float4 b1 = *(const float4*)&Bs[cur][k][tx * 8 + 4];
            float a[4] = {av.x, av.y, av.z, av.w};
            float b[8] = {b0.x, b0.y, b0.z, b0.w, b1.x, b1.y, b1.z, b1.w};
            #pragma unroll
            for (int i = 0; i < 4; ++i)
                #pragma unroll
                for (int j = 0; j < 8; ++j) acc[i][j] += a[i] * b[j];
        }
        if (kt + 1 < KT) {
            int nb = (kt + 1) & 1;
            As[nb][akq + 0][am0] = ra.x; As[nb][akq + 1][am0] = ra.y;
            As[nb][akq + 2][am0] = ra.z; As[nb][akq + 3][am0] = ra.w;
            int kr0 = tid >> 5, nq0 = (tid & 31) * 4;
            int idx1 = tid + 256;
            int kr1 = idx1 >> 5, nq1 = (idx1 & 31) * 4;
            *(float4*)&Bs[nb][kr0][nq0] = rb0;
            *(float4*)&Bs[nb][kr1][nq1] = rb1;
        }
        __syncthreads();
    }

    #pragma unroll
    for (int i = 0; i < 4; ++i) {
        int row = m0 + ty * 4 + i;
        if (row < cnt) {
            int tok = g_tok[e * T_ + row];
            float w = g_wt[e * T_ + row];
            float* op = Out + (size_t)tok * H_ + n0 + tx * 8;
            #pragma unroll
            for (int j = 0; j < 8; ++j) atomicAdd(op + j, w * acc[i][j]);
        }
    }
}

// ============================ launch ============================
extern "C" void kernel_launch(void* const* d_in, const int* in_sizes, int n_in,
                              void* d_out, int out_size)
{
    const float* x   = (const float*)d_in[0];
    const float* rw  = (const float*)d_in[1];
    const float* wg  = (const float*)d_in[2];
    const float* wu  = (const float*)d_in[3];
    const float* wd  = (const float*)d_in[4];
    const float* shg = (const float*)d_in[5];
    const float* shu = (const float*)d_in[6];
    const float* shd = (const float*)d_in[7];
    const float* seg = (const float*)d_in[8];
    float* out = (float*)d_out;

    init_kernel<<<1, 64>>>();
    router_kernel<<<T_, 256>>>(x, rw, seg);
    scan_kernel<<<1, 32>>>();

    // shared expert
    shared_upgate_kernel<<<dim3(SF_ / 64, T_ / 128), 256>>>(x, shg, shu);
    shared_down_kernel<<<dim3(H_ / 128, T_ / 128), 256>>>(shd, out);  // writes out

    // routed experts (accumulate into out)
    expert_upgate_kernel<<<dim3(F_ / 128, T_ / 64, E_), 256>>>(x, wg, wu);
    expert_down_kernel<<<dim3(H_ / 128, T_ / 64, E_), 256>>>(wd, out);
}

// round 3
// speedup vs baseline: 2.1281x; 2.1281x over previous
#include <cuda_runtime.h>
#include <math.h>
#include <stdint.h>

#define T_ 2048
#define H_ 2048
#define F_ 1408
#define E_ 60
#define TOPK_ 4
#define SF_ 5632

__device__ float g_S[(size_t)T_ * SF_];
__device__ float g_Hbuf[(size_t)T_ * TOPK_ * F_];
__device__ int   g_cnt[E_];
__device__ int   g_base[E_];
__device__ int   g_tok[E_ * T_];
__device__ float g_wt[E_ * T_];
__device__ float g_gate[T_];

__device__ __forceinline__ float siluf(float v) { return v / (1.f + expf(-v)); }
__device__ __forceinline__ uint32_t f2tf(float x) {
    uint32_t r; asm("cvt.rna.tf32.f32 %0, %1;" : "=r"(r) : "f"(x)); return r;
}
__device__ __forceinline__ void mma_tf32(float c[4], const uint32_t a[4], uint32_t b0, uint32_t b1) {
    asm volatile("mma.sync.aligned.m16n8k8.row.col.f32.tf32.tf32.f32 "
        "{%0,%1,%2,%3},{%4,%5,%6,%7},{%8,%9},{%0,%1,%2,%3};"
        : "+f"(c[0]), "+f"(c[1]), "+f"(c[2]), "+f"(c[3])
        : "r"(a[0]), "r"(a[1]), "r"(a[2]), "r"(a[3]), "r"(b0), "r"(b1));
}
__device__ __forceinline__ int bpos(int k) {
    return (k & 3) * 4 + ((k >> 2) & 1) + (k >> 3) * 2;
}

__global__ void init_kernel() { if (threadIdx.x < E_) g_cnt[threadIdx.x] = 0; }
__global__ void scan_kernel() {
    if (threadIdx.x == 0) {
        int s = 0;
        for (int e = 0; e < E_; ++e) { g_base[e] = s; s += g_cnt[e]; }
    }
}

__global__ __launch_bounds__(256) void router_kernel(
    const float* __restrict__ X, const float* __restrict__ RW,
    const float* __restrict__ SEG)
{
    int t = blockIdx.x;
    __shared__ float xs[H_];
    __shared__ float part[64][4];
    __shared__ float logits[E_];
    __shared__ float red[256];
    int tid = threadIdx.x;
    for (int i = tid; i < H_; i += 256) xs[i] = X[(size_t)t * H_ + i];
    __syncthreads();
    int e = tid >> 2, q = tid & 3;
    if (e < E_) {
        float s = 0.f;
        int h0 = q * (H_ / 4);
        for (int h = h0; h < h0 + H_ / 4; ++h) s += xs[h] * RW[(size_t)h * E_ + e];
        part[e][q] = s;
    }
    float gsum = 0.f;
    for (int i = tid; i < H_; i += 256) gsum += xs[i] * SEG[i];
    red[tid] = gsum;
    __syncthreads();
    if (e < E_ && q == 0) logits[e] = part[e][0] + part[e][1] + part[e][2] + part[e][3];
    for (int st = 128; st > 0; st >>= 1) {
        if (tid < st) red[tid] += red[tid + st];
        __syncthreads();
    }
    if (tid == 0) {
        g_gate[t] = 1.f / (1.f + expf(-red[0]));
        float mx = -1e30f;
        for (int i = 0; i < E_; ++i) mx = fmaxf(mx, logits[i]);
        float sum = 0.f;
        for (int i = 0; i < E_; ++i) { logits[i] = expf(logits[i] - mx); sum += logits[i]; }
        float inv = 1.f / sum;
        for (int k = 0; k < TOPK_; ++k) {
            int bi = 0; float bv = -1.f;
            for (int i = 0; i < E_; ++i) if (logits[i] > bv) { bv = logits[i]; bi = i; }
            logits[bi] = -1.f;
            int slot = atomicAdd(&g_cnt[bi], 1);
            g_tok[bi * T_ + slot] = t;
            g_wt[bi * T_ + slot]  = bv * inv;
        }
    }
}

// MODE 0: g_S = silu(X@B0)*(X@B1)          MODE 1: Out = gate*(g_S@B0)
// MODE 2: g_Hbuf = silu(Xg@B0e)*(Xg@B1e)   MODE 3: Out[tok] += w*(g_Hbuf@B0e)
template<int BM, int BN, int MODE, bool REM>
__global__ __launch_bounds__(128, 2) void gemm_tc(
    const float* __restrict__ A, const float* __restrict__ B0in,
    const float* __restrict__ B1in, float* __restrict__ Out)
{
    constexpr int K   = (MODE == 1) ? SF_ : ((MODE == 3) ? F_ : H_);
    constexpr int LDN = (MODE == 0) ? SF_ : ((MODE == 2) ? F_ : H_);
    constexpr bool DUAL = (MODE == 0) || (MODE == 2);
    constexpr int NB = DUAL ? 2 : 1;
    constexpr int SA = BM + 8;
    constexpr int MI = BM / 32, NI = BN / 16;
    constexpr int AV = BM / 32, BV = BN / 32;
    constexpr int KT = K / 16;

    __shared__ uint32_t As[2][16 * SA];
    __shared__ uint32_t Bsm[NB][2][BN * 17];
    __shared__ int toks[BM];

    const int tid = threadIdx.x, lane = tid & 31, warp = tid >> 5;
    const int lr = lane >> 2, lc = lane & 3;
    const int wm0 = (warp >> 1) * (BM / 2), wn0 = (warp & 1) * (BN / 2);
    const int n0 = blockIdx.x * BN;

    int e = 0, cnt = 0, pb = 0, m0 = 0;
    if constexpr (MODE >= 2) {
        e = blockIdx.z; cnt = g_cnt[e]; pb = g_base[e];
        if constexpr (!REM) { m0 = blockIdx.y * BM; if (m0 + BM > cnt) return; }
        else               { m0 = (cnt & ~127) + blockIdx.y * BM; if (m0 >= cnt) return; }
    } else {
        m0 = blockIdx.y * BM;
    }

    const float* Ap = (MODE == 1) ? (const float*)g_S
                    : (MODE == 3) ? (const float*)g_Hbuf : A;
    const float* Bp0 = B0in;
    const float* Bp1 = B1in;
    if constexpr (MODE >= 2) {
        size_t off = (size_t)e * K * LDN;
        Bp0 += off;
        if constexpr (DUAL) Bp1 += off;
    }

    if constexpr (MODE == 2) {
        if (tid < BM) {
            int mm = m0 + tid;
            toks[tid] = g_tok[e * T_ + (mm < cnt ? mm : cnt - 1)];
        }
        __syncthreads();
    }

    const float* arp[AV]; int asts[AV];
    #pragma unroll
    for (int i = 0; i < AV; ++i) {
        int idx = tid + i * 128;
        int r = idx % BM, kq = idx / BM;
        int gr;
        if constexpr (MODE == 2)      gr = toks[r];
        else if constexpr (MODE == 3) gr = pb + ((m0 + r < cnt) ? (m0 + r) : (cnt - 1));
        else                          gr = m0 + r;
        arp[i]  = Ap + (size_t)gr * K + kq * 4;
        asts[i] = kq * 4 * SA + r;
    }
    const float* brp0[BV]; const float* brp1[BV]; int bsts[BV];
    #pragma unroll
    for (int i = 0; i < BV; ++i) {
        int idx = tid + i * 128;
        int q = idx % (BN / 4), k = idx / (BN / 4);
        brp0[i] = Bp0 + (size_t)k * LDN + n0 + q * 4;
        if constexpr (DUAL) brp1[i] = Bp1 + (size_t)k * LDN + n0 + q * 4;
        bsts[i] = q * 4 * 17 + bpos(k);
    }

    float acc0[MI][NI][4];
    float acc1[DUAL ? MI : 1][DUAL ? NI : 1][4];
    #pragma unroll
    for (int mi = 0; mi < MI; ++mi)
        #pragma unroll
        for (int ni = 0; ni < NI; ++ni)
            #pragma unroll
            for (int j = 0; j < 4; ++j) {
                acc0[mi][ni][j] = 0.f;
                if constexpr (DUAL) acc1[mi][ni][j] = 0.f;
            }

    float4 ra[AV], rb0[BV], rb1[BV];
    auto do_sts = [&](int b) {
        #pragma unroll
        for (int i = 0; i < AV; ++i) {
            uint32_t* p = &As[b][asts[i]];
            p[0] = f2tf(ra[i].x); p[SA] = f2tf(ra[i].y);
            p[2 * SA] = f2tf(ra[i].z); p[3 * SA] = f2tf(ra[i].w);
        }
        #pragma unroll
        for (int i = 0; i < BV; ++i) {
            uint32_t* p = &Bsm[0][b][bsts[i]];
            p[0] = f2tf(rb0[i].x); p[17] = f2tf(rb0[i].y);
            p[34] = f2tf(rb0[i].z); p[51] = f2tf(rb0[i].w);
            if constexpr (DUAL) {
                uint32_t* q2 = &Bsm[1][b][bsts[i]];
                q2[0] = f2tf(rb1[i].x); q2[17] = f2tf(rb1[i].y);
                q2[34] = f2tf(rb1[i].z); q2[51] = f2tf(rb1[i].w);
            }
        }
    };

    #pragma unroll
    for (int i = 0; i < AV; ++i) ra[i] = *(const float4*)arp[i];
    #pragma unroll
    for (int i = 0; i < BV; ++i) {
        rb0[i] = *(const float4*)brp0[i];
        if constexpr (DUAL) rb1[i] = *(const float4*)brp1[i];
    }
    do_sts(0);
    __syncthreads();

    for (int kt = 0; kt < KT; ++kt) {
        int cur = kt & 1;
        if (kt + 1 < KT) {
            int k0 = (kt + 1) * 16;
            #pragma unroll
            for (int i = 0; i < AV; ++i) ra[i] = *(const float4*)(arp[i] + k0);
            #pragma unroll
            for (int i = 0; i < BV; ++i) {
                rb0[i] = *(const float4*)(brp0[i] + (size_t)k0 * LDN);
                if constexpr (DUAL) rb1[i] = *(const float4*)(brp1[i] + (size_t)k0 * LDN);
            }
        }
        #pragma unroll
        for (int s = 0; s < 2; ++s) {
            uint32_t af[MI][4];
            #pragma unroll
            for (int mi = 0; mi < MI; ++mi) {
                int m = wm0 + mi * 16 + lr;
                int kk = 8 * s + lc;
                af[mi][0] = As[cur][kk * SA + m];
                af[mi][1] = As[cur][kk * SA + m + 8];
                af[mi][2] = As[cur][(kk + 4) * SA + m];
                af[mi][3] = As[cur][(kk + 4) * SA + m + 8];
            }
            #pragma unroll
            for (int ni = 0; ni < NI; ++ni) {
                int bi = (wn0 + ni * 8 + lr) * 17 + lc * 4 + 2 * s;
                uint32_t b0 = Bsm[0][cur][bi], b1 = Bsm[0][cur][bi + 1];
                #pragma unroll
                for (int mi = 0; mi < MI; ++mi) mma_tf32(acc0[mi][ni], af[mi], b0, b1);
                if constexpr (DUAL) {
                    uint32_t c0 = Bsm[1][cur][bi], c1 = Bsm[1][cur][bi + 1];
                    #pragma unroll
                    for (int mi = 0; mi < MI; ++mi) mma_tf32(acc1[mi][ni], af[mi], c0, c1);
                }
            }
        }
        if (kt + 1 < KT) do_sts((kt + 1) & 1);
        __syncthreads();
    }

    #pragma unroll
    for (int mi = 0; mi < MI; ++mi) {
        #pragma unroll
        for (int h = 0; h < 2; ++h) {
            int rloc = wm0 + mi * 16 + lr + 8 * h;
            if constexpr (MODE == 0) {
                int row = m0 + rloc;
                #pragma unroll
                for (int ni = 0; ni < NI; ++ni) {
                    int col = n0 + wn0 + ni * 8 + lc * 2;
                    float2 o;
                    o.x = siluf(acc0[mi][ni][2 * h]) * acc1[mi][ni][2 * h];
                    o.y = siluf(acc0[mi][ni][2 * h + 1]) * acc1[mi][ni][2 * h + 1];
                    *(float2*)&g_S[(size_t)row * SF_ + col] = o;
                }
            } else if constexpr (MODE == 1) {
                int row = m0 + rloc;
                float gt = g_gate[row];
                #pragma unroll
                for (int ni = 0; ni < NI; ++ni) {
                    int col = n0 + wn0 + ni * 8 + lc * 2;
                    float2 o;
                    o.x = gt * acc0[mi][ni][2 * h];
                    o.y = gt * acc0[mi][ni][2 * h + 1];
                    *(float2*)&Out[(size_t)row * H_ + col] = o;
                }
            } else if constexpr (MODE == 2) {
                int re = m0 + rloc;
                if (re < cnt) {
                    size_t rowp = (size_t)(pb + re) * F_;
                    #pragma unroll
                    for (int ni = 0; ni < NI; ++ni) {
                        int col = n0 + wn0 + ni * 8 + lc * 2;
                        float2 o;
                        o.x = siluf(acc0[mi][ni][2 * h]) * acc1[mi][ni][2 * h];
                        o.y = siluf(acc0[mi][ni][2 * h + 1]) * acc1[mi][ni][2 * h + 1];
                        *(float2*)&g_Hbuf[rowp + col] = o;
                    }
                }
            } else {
                int re = m0 + rloc;
                if (re < cnt) {
                    int tk = g_tok[e * T_ + re];
                    float w = g_wt[e * T_ + re];
                    float* op = Out + (size_t)tk * H_;
                    #pragma unroll
                    for (int ni = 0; ni < NI; ++ni) {
                        int col = n0 + wn0 + ni * 8 + lc * 2;
                        atomicAdd(op + col,     w * acc0[mi][ni][2 * h]);
                        atomicAdd(op + col + 1, w * acc0[mi][ni][2 * h + 1]);
                    }
                }
            }
        }
    }
}

extern "C" void kernel_launch(void* const* d_in, const int* in_sizes, int n_in,
                              void* d_out, int out_size)
{
    const float* x   = (const float*)d_in[0];
    const float* rw  = (const float*)d_in[1];
    const float* wg  = (const float*)d_in[2];
    const float* wu  = (const float*)d_in[3];
    const float* wd  = (const float*)d_in[4];
    const float* shg = (const float*)d_in[5];
    const float* shu = (const float*)d_in[6];
    const float* shd = (const float*)d_in[7];
    const float* seg = (const float*)d_in[8];
    float* out = (float*)d_out;

    init_kernel<<<1, 64>>>();
    router_kernel<<<T_, 256>>>(x, rw, seg);
    scan_kernel<<<1, 32>>>();

    gemm_tc<128, 64, 0, false><<<dim3(SF_ / 64, T_ / 128), 128>>>(x, shg, shu, nullptr);
    gemm_tc<128, 128, 1, false><<<dim3(H_ / 128, T_ / 128), 128>>>(nullptr, shd, nullptr, out);

    gemm_tc<128, 64, 2, false><<<dim3(F_ / 64, T_ / 128, E_), 128>>>(x, wg, wu, nullptr);
    gemm_tc<32, 64, 2, true><<<dim3(F_ / 64, 4, E_), 128>>>(x, wg, wu, nullptr);
    gemm_tc<128, 128, 3, false><<<dim3(H_ / 128, T_ / 128, E_), 128>>>(nullptr, wd, nullptr, out);
    gemm_tc<32, 128, 3, true><<<dim3(H_ / 128, 4, E_), 128>>>(nullptr, wd, nullptr, out);
}

// round 5
// speedup vs baseline: 3.8156x; 1.7930x over previous
#include <cuda_runtime.h>
#include <cuda_fp16.h>
#include <math.h>
#include <stdint.h>

#define T_ 2048
#define H_ 2048
#define F_ 1408
#define E_ 60
#define TOPK_ 4
#define SF_ 5632

__device__ __half g_S[(size_t)T_ * SF_];
__device__ __half g_Hbuf[(size_t)T_ * TOPK_ * F_];
__device__ int   g_cnt[E_];
__device__ int   g_base[E_];
__device__ int   g_tok[E_ * T_];
__device__ float g_wt[E_ * T_];
__device__ float g_gate[T_];

__device__ __forceinline__ float siluf(float v) { return v / (1.f + expf(-v)); }
__device__ __forceinline__ uint32_t f2h2(float x, float y) {
    __half2 h = __floats2half2_rn(x, y);
    return *(uint32_t*)&h;
}
__device__ __forceinline__ uint32_t smem_u32(const void* p) {
    uint32_t a; asm("{ .reg .u64 t; cvta.to.shared.u64 t, %1; cvt.u32.u64 %0, t; }" : "=r"(a) : "l"(p)); return a;
}
#define SWZ(x) ((x) ^ (((x) >> 3) & 0x70))

__device__ __forceinline__ void ldsm4(uint32_t r[4], uint32_t a) {
    asm volatile("ldmatrix.sync.aligned.m8n8.x4.shared.b16 {%0,%1,%2,%3}, [%4];"
        : "=r"(r[0]), "=r"(r[1]), "=r"(r[2]), "=r"(r[3]) : "r"(a));
}
__device__ __forceinline__ void ldsm2t(uint32_t& r0, uint32_t& r1, uint32_t a) {
    asm volatile("ldmatrix.sync.aligned.m8n8.x2.trans.shared.b16 {%0,%1}, [%2];"
        : "=r"(r0), "=r"(r1) : "r"(a));
}
__device__ __forceinline__ void mma_f16(float c[4], const uint32_t a[4], uint32_t b0, uint32_t b1) {
    asm volatile("mma.sync.aligned.m16n8k16.row.col.f32.f16.f16.f32 "
        "{%0,%1,%2,%3},{%4,%5,%6,%7},{%8,%9},{%0,%1,%2,%3};"
        : "+f"(c[0]), "+f"(c[1]), "+f"(c[2]), "+f"(c[3])
        : "r"(a[0]), "r"(a[1]), "r"(a[2]), "r"(a[3]), "r"(b0), "r"(b1));
}

__global__ void init_kernel() { if (threadIdx.x < E_) g_cnt[threadIdx.x] = 0; }
__global__ void scan_kernel() {
    if (threadIdx.x == 0) {
        int s = 0;
        for (int e = 0; e < E_; ++e) { g_base[e] = s; s += g_cnt[e]; }
    }
}

__global__ __launch_bounds__(256) void router_kernel(
    const float* __restrict__ X, const float* __restrict__ RW,
    const float* __restrict__ SEG)
{
    int t = blockIdx.x;
    __shared__ float xs[H_];
    __shared__ float part[64][4];
    __shared__ float logits[E_];
    __shared__ float red[256];
    int tid = threadIdx.x;
    for (int i = tid; i < H_; i += 256) xs[i] = X[(size_t)t * H_ + i];
    __syncthreads();
    int e = tid >> 2, q = tid & 3;
    if (e < E_) {
        float s = 0.f;
        int h0 = q * (H_ / 4);
        for (int h = h0; h < h0 + H_ / 4; ++h) s += xs[h] * RW[(size_t)h * E_ + e];
        part[e][q] = s;
    }
    float gsum = 0.f;
    for (int i = tid; i < H_; i += 256) gsum += xs[i] * SEG[i];
    red[tid] = gsum;
    __syncthreads();
    if (e < E_ && q == 0) logits[e] = part[e][0] + part[e][1] + part[e][2] + part[e][3];
    for (int st = 128; st > 0; st >>= 1) {
        if (tid < st) red[tid] += red[tid + st];
        __syncthreads();
    }
    if (tid == 0) {
        g_gate[t] = 1.f / (1.f + expf(-red[0]));
        float mx = -1e30f;
        for (int i = 0; i < E_; ++i) mx = fmaxf(mx, logits[i]);
        float sum = 0.f;
        for (int i = 0; i < E_; ++i) { logits[i] = expf(logits[i] - mx); sum += logits[i]; }
        float inv = 1.f / sum;
        for (int k = 0; k < TOPK_; ++k) {
            int bi = 0; float bv = -1.f;
            for (int i = 0; i < E_; ++i) if (logits[i] > bv) { bv = logits[i]; bi = i; }
            logits[bi] = -1.f;
            int slot = atomicAdd(&g_cnt[bi], 1);
            g_tok[bi * T_ + slot] = t;
            g_wt[bi * T_ + slot]  = bv * inv;
        }
    }
}

// FP16 tensor-core grouped GEMM. 128 threads.
// MODE 0: g_S    = silu(X@B0)*(X@B1)            (A fp32, dual B, BN=64)
// MODE 1: Out    = gate*(g_S@B0)                (A fp16, single B, BN=128)
// MODE 2: g_Hbuf = silu(Xg@B0e)*(Xg@B1e)        (A fp32 gathered, dual, BN=64)
// MODE 3: Out[tok] += w*(g_Hbuf@B0e)            (A fp16, single, BN=128)
// A smem: rows of 16 halves padded to 48B (conflict-free ldmatrix.x4).
// B smem: k-major SW128 panels of [16k x 64n] (coalesced STS, ldmatrix.x2.trans).
template<int BM, int MODE>
__global__ __launch_bounds__(128) void hgemm(
    const float* __restrict__ A, const float* __restrict__ B0,
    const float* __restrict__ B1, float* __restrict__ Out)
{
    constexpr int K    = (MODE == 1) ? SF_ : ((MODE == 3) ? F_ : H_);
    constexpr int LDN  = (MODE == 0) ? SF_ : ((MODE == 2) ? F_ : H_);
    constexpr bool DUAL = (MODE == 0) || (MODE == 2);
    constexpr bool AHALF = (MODE == 1) || (MODE == 3);
    constexpr int BN   = DUAL ? 64 : 128;
    constexpr int NMAT = DUAL ? 2 : 1;
    constexpr int NWC  = (BM == 128) ? 2 : 4;       // warp cols
    constexpr int WM   = BM / (4 / NWC);
    constexpr int WN   = BN / NWC;
    constexpr int MI   = WM / 16, NI = WN / 8;
    constexpr int KT   = K / 16;
    constexpr int ABYTES = BM * 48;
    constexpr int BBYTES = 16 * BN * 2;
    constexpr int AV   = AHALF ? ((BM * 2 + 127) / 128) : ((BM * 4 + 127) / 128);
    constexpr int BV   = (16 * (BN / 8) + 127) / 128;

    __shared__ __align__(16) char Asm[2 * ABYTES];
    __shared__ __align__(16) char Bsm[NMAT * 2 * BBYTES];
    __shared__ int toks[BM];

    const int tid = threadIdx.x, lane = tid & 31, warp = tid >> 5;
    const int lr = lane >> 2, lc = lane & 3;
    const int wm0 = (warp / NWC) * WM, wn0 = (warp % NWC) * WN;
    const int n0 = blockIdx.x * BN;

    int e = 0, cnt = 0, pb = 0, m0;
    if constexpr (MODE >= 2) {
        e = blockIdx.z; cnt = g_cnt[e]; pb = g_base[e];
        if constexpr (BM == 128) { m0 = blockIdx.y * 128; if (m0 + 128 > cnt) return; }
        else                     { m0 = (cnt & ~127) + blockIdx.y * 32; if (m0 >= cnt) return; }
    } else m0 = blockIdx.y * BM;

    const float* Bp0 = B0;
    const float* Bp1 = DUAL ? B1 : B0;
    if constexpr (MODE >= 2) {
        size_t off = (size_t)e * K * LDN;
        Bp0 += off; Bp1 += off;
    }
    if constexpr (MODE == 2) {
        if (tid < BM) { int mm = m0 + tid; toks[tid] = g_tok[e * T_ + (mm < cnt ? mm : cnt - 1)]; }
        __syncthreads();
    }

    // ---- loader assignments ----
    const void* asrc[AV]; int adst[AV];
    #pragma unroll
    for (int l = 0; l < AV; ++l) {
        if constexpr (!AHALF) {
            int idx = (tid + l * 128) % (BM * 4);
            int row = idx >> 2, kq = idx & 3;
            const float* base;
            if constexpr (MODE == 0) base = A + (size_t)(m0 + row) * H_;
            else                     base = A + (size_t)toks[row] * H_;
            asrc[l] = base + kq * 4;
            adst[l] = row * 48 + kq * 8;
        } else {
            int idx = (tid + l * 128) % (BM * 2);
            int row = idx >> 1, kq8 = idx & 1;
            const __half* base;
            if constexpr (MODE == 1) base = g_S + (size_t)(m0 + row) * SF_;
            else { int rr = m0 + row; base = g_Hbuf + (size_t)(pb + (rr < cnt ? rr : cnt - 1)) * F_; }
            asrc[l] = base + kq8 * 8;
            adst[l] = row * 48 + kq8 * 16;
        }
    }
    size_t bsrc[BV]; int bdst[BV];
    #pragma unroll
    for (int l = 0; l < BV; ++l) {
        int idx = tid + l * 128;
        int k = idx / (BN / 8), seg = idx % (BN / 8), n = seg * 8;
        bsrc[l] = (size_t)k * LDN + n0 + n;
        bdst[l] = (n >> 6) * 2048 + SWZ(k * 128 + (n & 63) * 2);
    }

    // ---- fragment addresses ----
    const uint32_t asb = smem_u32(Asm), bsb = smem_u32(Bsm);
    const uint32_t aaddr0 = asb + (uint32_t)((wm0 + (lane & 15)) * 48 + (lane >> 4) * 16);
    uint32_t bni[NI];
    {
        int kb = lane & 15;
        #pragma unroll
        for (int ni = 0; ni < NI; ++ni) {
            int n = wn0 + ni * 8;
            bni[ni] = (uint32_t)((n >> 6) * 2048 + SWZ(kb * 128 + (n & 63) * 2));
        }
    }

    float acc[NMAT][MI][NI][4];
    #pragma unroll
    for (int m = 0; m < NMAT; ++m)
        #pragma unroll
        for (int mi = 0; mi < MI; ++mi)
            #pragma unroll
            for (int ni = 0; ni < NI; ++ni)
                #pragma unroll
                for (int j = 0; j < 4; ++j) acc[m][mi][ni][j] = 0.f;

    float4 raf[AV]; uint4 rah[AV];
    float4 rb[NMAT][BV][2];

    auto fetch = [&](int c) {
        #pragma unroll
        for (int l = 0; l < AV; ++l) {
            if constexpr (!AHALF) raf[l] = *(const float4*)((const float*)asrc[l] + c * 16);
            else                  rah[l] = *(const uint4*)((const __half*)asrc[l] + c * 16);
        }
        #pragma unroll
        for (int m = 0; m < NMAT; ++m) {
            const float* bp = (m == 0 ? Bp0 : Bp1) + (size_t)c * 16 * LDN;
            #pragma unroll
            for (int l = 0; l < BV; ++l) {
                rb[m][l][0] = *(const float4*)(bp + bsrc[l]);
                rb[m][l][1] = *(const float4*)(bp + bsrc[l] + 4);
            }
        }
    };
    auto sts = [&](int buf) {
        #pragma unroll
        for (int l = 0; l < AV; ++l) {
            char* p = Asm + buf * ABYTES + adst[l];
            if constexpr (!AHALF)
                *(uint2*)p = make_uint2(f2h2(raf[l].x, raf[l].y), f2h2(raf[l].z, raf[l].w));
            else
                *(uint4*)p = rah[l];
        }
        #pragma unroll
        for (int m = 0; m < NMAT; ++m) {
            #pragma unroll
            for (int l = 0; l < BV; ++l) {
                char* p = Bsm + (m * 2 + buf) * BBYTES + bdst[l];
                *(uint4*)p = make_uint4(
                    f2h2(rb[m][l][0].x, rb[m][l][0].y), f2h2(rb[m][l][0].z, rb[m][l][0].w),
                    f2h2(rb[m][l][1].x, rb[m][l][1].y), f2h2(rb[m][l][1].z, rb[m][l][1].w));
            }
        }
    };

    fetch(0);
    sts(0);
    __syncthreads();

    #pragma unroll 1
    for (int c = 0; c < KT; ++c) {
        const int cur = c & 1;
        if (c + 1 < KT) fetch(c + 1);
        uint32_t a[MI][4];
        #pragma unroll
        for (int mi = 0; mi < MI; ++mi) ldsm4(a[mi], aaddr0 + cur * ABYTES + mi * 768);
        #pragma unroll
        for (int m = 0; m < NMAT; ++m) {
            const uint32_t bb = bsb + (m * 2 + cur) * BBYTES;
            #pragma unroll
            for (int ni = 0; ni < NI; ++ni) {
                uint32_t b0, b1;
                ldsm2t(b0, b1, bb + bni[ni]);
                #pragma unroll
                for (int mi = 0; mi < MI; ++mi) mma_f16(acc[m][mi][ni], a[mi], b0, b1);
            }
        }
        if (c + 1 < KT) sts((c + 1) & 1);
        __syncthreads();
    }

    // ---- epilogue ----
    #pragma unroll
    for (int mi = 0; mi < MI; ++mi) {
        #pragma unroll
        for (int h = 0; h < 2; ++h) {
            int rloc = wm0 + mi * 16 + lr + 8 * h;
            if constexpr (MODE == 0) {
                int row = m0 + rloc;
                #pragma unroll
                for (int ni = 0; ni < NI; ++ni) {
                    int col = n0 + wn0 + ni * 8 + lc * 2;
                    float g0 = acc[0][mi][ni][2 * h], g1 = acc[0][mi][ni][2 * h + 1];
                    float u0 = acc[1][mi][ni][2 * h], u1 = acc[1][mi][ni][2 * h + 1];
                    *(__half2*)&g_S[(size_t)row * SF_ + col] =
                        __floats2half2_rn(siluf(g0) * u0, siluf(g1) * u1);
                }
            } else if constexpr (MODE == 1) {
                int row = m0 + rloc;
                float gt = g_gate[row];
                #pragma unroll
                for (int ni = 0; ni < NI; ++ni) {
                    int col = n0 + wn0 + ni * 8 + lc * 2;
                    float2 o = make_float2(gt * acc[0][mi][ni][2 * h], gt * acc[0][mi][ni][2 * h + 1]);
                    *(float2*)&Out[(size_t)row * H_ + col] = o;
                }
            } else if constexpr (MODE == 2) {
                int rr = m0 + rloc;
                if (rr < cnt) {
                    size_t rp = (size_t)(pb + rr) * F_;
                    #pragma unroll
                    for (int ni = 0; ni < NI; ++ni) {
                        int col = n0 + wn0 + ni * 8 + lc * 2;
                        float g0 = acc[0][mi][ni][2 * h], g1 = acc[0][mi][ni][2 * h + 1];
                        float u0 = acc[1][mi][ni][2 * h], u1 = acc[1][mi][ni][2 * h + 1];
                        *(__half2*)&g_Hbuf[rp + col] =
                            __floats2half2_rn(siluf(g0) * u0, siluf(g1) * u1);
                    }
                }
            } else {
                int rr = m0 + rloc;
                if (rr < cnt) {
                    int tk = g_tok[e * T_ + rr];
                    float w = g_wt[e * T_ + rr];
                    float* op = Out + (size_t)tk * H_;
                    #pragma unroll
                    for (int ni = 0; ni < NI; ++ni) {
                        int col = n0 + wn0 + ni * 8 + lc * 2;
                        atomicAdd(op + col,     w * acc[0][mi][ni][2 * h]);
                        atomicAdd(op + col + 1, w * acc[0][mi][ni][2 * h + 1]);
                    }
                }
            }
        }
    }
}

extern "C" void kernel_launch(void* const* d_in, const int* in_sizes, int n_in,
                              void* d_out, int out_size)
{
    const float* x   = (const float*)d_in[0];
    const float* rw  = (const float*)d_in[1];
    const float* wg  = (const float*)d_in[2];
    const float* wu  = (const float*)d_in[3];
    const float* wd  = (const float*)d_in[4];
    const float* shg = (const float*)d_in[5];
    const float* shu = (const float*)d_in[6];
    const float* shd = (const float*)d_in[7];
    const float* seg = (const float*)d_in[8];
    float* out = (float*)d_out;

    init_kernel<<<1, 64>>>();
    router_kernel<<<T_, 256>>>(x, rw, seg);
    scan_kernel<<<1, 32>>>();

    // shared expert up/gate, then routed up/gate (full + remainder tiles)
    hgemm<128, 0><<<dim3(SF_ / 64, T_ / 128), 128>>>(x, shg, shu, nullptr);
    hgemm<128, 2><<<dim3(F_ / 64, T_ / 128, E_), 128>>>(x, wg, wu, nullptr);
    hgemm<32, 2><<<dim3(F_ / 64, 4, E_), 128>>>(x, wg, wu, nullptr);

    // shared down (initializes Out), then routed down (accumulates)
    hgemm<128, 1><<<dim3(H_ / 128, T_ / 128), 128>>>(nullptr, shd, nullptr, out);
    hgemm<128, 3><<<dim3(H_ / 128, T_ / 128, E_), 128>>>(nullptr, wd, nullptr, out);
    hgemm<32, 3><<<dim3(H_ / 128, 4, E_), 128>>>(nullptr, wd, nullptr, out);
}

// round 6
// speedup vs baseline: 4.9011x; 1.2845x over previous
#include <cuda_runtime.h>
#include <cuda_fp16.h>
#include <math.h>
#include <stdint.h>

#define T_ 2048
#define H_ 2048
#define F_ 1408
#define E_ 60
#define TOPK_ 4
#define SF_ 5632

__device__ __half g_Xh[(size_t)T_ * H_];
__device__ __half g_S[(size_t)T_ * SF_];
__device__ __half g_Hbuf[(size_t)T_ * TOPK_ * F_];
__device__ int   g_cnt[E_];
__device__ int   g_base[E_];
__device__ int   g_tok[E_ * T_];
__device__ float g_wt[E_ * T_];
__device__ float g_gate[T_];

__device__ __forceinline__ float siluf(float v) { return v / (1.f + expf(-v)); }
__device__ __forceinline__ uint32_t f2h2(float x, float y) {
    __half2 h = __floats2half2_rn(x, y);
    return *(uint32_t*)&h;
}
__device__ __forceinline__ uint32_t smem_u32(const void* p) {
    uint32_t a; asm("{ .reg .u64 t; cvta.to.shared.u64 t, %1; cvt.u32.u64 %0, t; }" : "=r"(a) : "l"(p)); return a;
}
#define SWZ(x) ((x) ^ (((x) >> 3) & 0x70))

__device__ __forceinline__ void ldsm4(uint32_t r[4], uint32_t a) {
    asm volatile("ldmatrix.sync.aligned.m8n8.x4.shared.b16 {%0,%1,%2,%3}, [%4];"
        : "=r"(r[0]), "=r"(r[1]), "=r"(r[2]), "=r"(r[3]) : "r"(a));
}
__device__ __forceinline__ void ldsm2t(uint32_t& r0, uint32_t& r1, uint32_t a) {
    asm volatile("ldmatrix.sync.aligned.m8n8.x2.trans.shared.b16 {%0,%1}, [%2];"
        : "=r"(r0), "=r"(r1) : "r"(a));
}
__device__ __forceinline__ void mma_f16(float c[4], const uint32_t a[4], uint32_t b0, uint32_t b1) {
    asm volatile("mma.sync.aligned.m16n8k16.row.col.f32.f16.f16.f32 "
        "{%0,%1,%2,%3},{%4,%5,%6,%7},{%8,%9},{%0,%1,%2,%3};"
        : "+f"(c[0]), "+f"(c[1]), "+f"(c[2]), "+f"(c[3])
        : "r"(a[0]), "r"(a[1]), "r"(a[2]), "r"(a[3]), "r"(b0), "r"(b1));
}

__global__ void init_kernel() { if (threadIdx.x < E_) g_cnt[threadIdx.x] = 0; }
__global__ void scan_kernel() {
    if (threadIdx.x == 0) {
        int s = 0;
        for (int e = 0; e < E_; ++e) { g_base[e] = s; s += g_cnt[e]; }
    }
}
// X (fp32) -> g_Xh (fp16), 8 elems/thread
__global__ __launch_bounds__(256) void convx_kernel(const float* __restrict__ X) {
    size_t i = ((size_t)blockIdx.x * 256 + threadIdx.x) * 8;
    float4 a = *(const float4*)(X + i);
    float4 b = *(const float4*)(X + i + 4);
    uint4 o = make_uint4(f2h2(a.x, a.y), f2h2(a.z, a.w), f2h2(b.x, b.y), f2h2(b.z, b.w));
    *(uint4*)&g_Xh[i] = o;
}

__global__ __launch_bounds__(256) void router_kernel(
    const float* __restrict__ X, const float* __restrict__ RW,
    const float* __restrict__ SEG)
{
    int t = blockIdx.x;
    __shared__ float xs[H_];
    __shared__ float part[64][4];
    __shared__ float logits[E_];
    __shared__ float red[256];
    int tid = threadIdx.x;
    for (int i = tid; i < H_; i += 256) xs[i] = X[(size_t)t * H_ + i];
    __syncthreads();
    int e = tid >> 2, q = tid & 3;
    if (e < E_) {
        float s = 0.f;
        int h0 = q * (H_ / 4);
        for (int h = h0; h < h0 + H_ / 4; ++h) s += xs[h] * RW[(size_t)h * E_ + e];
        part[e][q] = s;
    }
    float gsum = 0.f;
    for (int i = tid; i < H_; i += 256) gsum += xs[i] * SEG[i];
    red[tid] = gsum;
    __syncthreads();
    if (e < E_ && q == 0) logits[e] = part[e][0] + part[e][1] + part[e][2] + part[e][3];
    for (int st = 128; st > 0; st >>= 1) {
        if (tid < st) red[tid] += red[tid + st];
        __syncthreads();
    }
    if (tid == 0) {
        g_gate[t] = 1.f / (1.f + expf(-red[0]));
        float mx = -1e30f;
        for (int i = 0; i < E_; ++i) mx = fmaxf(mx, logits[i]);
        float sum = 0.f;
        for (int i = 0; i < E_; ++i) { logits[i] = expf(logits[i] - mx); sum += logits[i]; }
        float inv = 1.f / sum;
        for (int k = 0; k < TOPK_; ++k) {
            int bi = 0; float bv = -1.f;
            for (int i = 0; i < E_; ++i) if (logits[i] > bv) { bv = logits[i]; bi = i; }
            logits[bi] = -1.f;
            int slot = atomicAdd(&g_cnt[bi], 1);
            g_tok[bi * T_ + slot] = t;
            g_wt[bi * T_ + slot]  = bv * inv;
        }
    }
}

// FP16 tensor-core grouped GEMM, BK=32, double-buffered.
// MODE 0: g_S    = silu(Xh@B0)*(Xh@B1)      (dual, BN=64)
// MODE 1: Out    = gate*(g_S@B0)            (single, BN=128)
// MODE 2: g_Hbuf = silu(Xh[g]@B0e)*(Xh[g]@B1e)
// MODE 3: Out[tok] += w*(g_Hbuf@B0e)
// A smem: BM rows x 32 halves, row stride 80B. B smem: k-major SW128 panels
// (32k x 64n = 4KB each), fp32->fp16 converted at STS.
template<int BM, int MODE>
__global__ __launch_bounds__((BM == 128) ? 256 : 128, 2) void hgemm(
    const float* __restrict__ B0, const float* __restrict__ B1,
    float* __restrict__ Out)
{
    constexpr int THREADS = (BM == 128) ? 256 : 128;
    constexpr int K    = (MODE == 1) ? SF_ : ((MODE == 3) ? F_ : H_);
    constexpr int LDN  = (MODE == 0) ? SF_ : ((MODE == 2) ? F_ : H_);
    constexpr bool DUAL = (MODE == 0) || (MODE == 2);
    constexpr int NMAT = DUAL ? 2 : 1;
    constexpr int BN   = DUAL ? 64 : 128;
    constexpr int NW   = THREADS / 32;
    constexpr int WC   = (BM == 128 && DUAL) ? 2 : 4;
    constexpr int WR   = NW / WC;
    constexpr int WM   = BM / WR;
    constexpr int WN   = BN / WC;
    constexpr int MI   = WM / 16, NI = WN / 8;
    constexpr int KT   = K / 32;
    constexpr int ABYTES = BM * 80;
    constexpr int BBYTES = (BN / 64) * 4096;          // per (mat,buf)
    constexpr int AV   = BM * 4 / THREADS;            // uint4 slots (8 halves)
    constexpr int BS8  = 32 * (BN / 8) / THREADS;     // 8-col fp32 slots per mat

    __shared__ __align__(16) char Asm[2 * ABYTES];
    __shared__ __align__(16) char Bsm[NMAT * 2 * BBYTES];
    __shared__ int toks[BM];

    const int tid = threadIdx.x, lane = tid & 31, warp = tid >> 5;
    const int lr = lane >> 2, lc = lane & 3;
    const int wm0 = (warp / WC) * WM, wn0 = (warp % WC) * WN;
    const int n0 = blockIdx.x * BN;

    int e = 0, cnt = 0, pb = 0, m0;
    if constexpr (MODE >= 2) {
        e = blockIdx.z; cnt = g_cnt[e]; pb = g_base[e];
        if constexpr (BM == 128) { m0 = blockIdx.y * 128; if (m0 + 128 > cnt) return; }
        else                     { m0 = (cnt & ~127) + blockIdx.y * 32; if (m0 >= cnt) return; }
    } else m0 = blockIdx.y * BM;

    const float* Bp0 = B0;
    const float* Bp1 = DUAL ? B1 : B0;
    if constexpr (MODE >= 2) {
        size_t off = (size_t)e * K * LDN;
        Bp0 += off; Bp1 += off;
    }
    if constexpr (MODE == 2) {
        if (tid < BM) { int mm = m0 + tid; toks[tid] = g_tok[e * T_ + (mm < cnt ? mm : cnt - 1)]; }
        __syncthreads();
    }

    // ---- loader assignments ----
    const __half* asrc[AV]; int adst[AV];
    #pragma unroll
    for (int l = 0; l < AV; ++l) {
        int idx = tid + l * THREADS;
        int row = idx >> 2, kq = idx & 3;
        const __half* base;
        if constexpr (MODE == 0)      base = g_Xh + (size_t)(m0 + row) * H_;
        else if constexpr (MODE == 1) base = g_S + (size_t)(m0 + row) * SF_;
        else if constexpr (MODE == 2) base = g_Xh + (size_t)toks[row] * H_;
        else { int rr = m0 + row; base = g_Hbuf + (size_t)(pb + (rr < cnt ? rr : cnt - 1)) * F_; }
        asrc[l] = base + kq * 8;
        adst[l] = row * 80 + kq * 16;
    }
    size_t bsrc[BS8]; int bdst[BS8];
    #pragma unroll
    for (int l = 0; l < BS8; ++l) {
        int idx = tid + l * THREADS;
        int k = idx / (BN / 8), n = (idx % (BN / 8)) * 8;
        bsrc[l] = (size_t)k * LDN + n0 + n;
        bdst[l] = (n >> 6) * 4096 + SWZ(k * 128 + (n & 63) * 2);
    }

    // ---- fragment addresses ----
    const uint32_t asb = smem_u32(Asm), bsb = smem_u32(Bsm);
    const uint32_t aaddr0 = asb + (uint32_t)((wm0 + (lane & 15)) * 80 + (lane >> 4) * 16);
    uint32_t bni[NI];
    #pragma unroll
    for (int ni = 0; ni < NI; ++ni) {
        int n = wn0 + ni * 8;
        bni[ni] = (uint32_t)((n >> 6) * 4096 + SWZ((lane & 15) * 128 + (n & 63) * 2));
    }

    float acc[NMAT][MI][NI][4];
    #pragma unroll
    for (int m = 0; m < NMAT; ++m)
        #pragma unroll
        for (int mi = 0; mi < MI; ++mi)
            #pragma unroll
            for (int ni = 0; ni < NI; ++ni)
                #pragma unroll
                for (int j = 0; j < 4; ++j) acc[m][mi][ni][j] = 0.f;

    uint4 rah[AV];
    float4 rb[NMAT][BS8][2];

    auto fetch = [&](int c) {
        #pragma unroll
        for (int l = 0; l < AV; ++l) rah[l] = *(const uint4*)(asrc[l] + c * 32);
        #pragma unroll
        for (int m = 0; m < NMAT; ++m) {
            const float* bp = (m == 0 ? Bp0 : Bp1) + (size_t)c * 32 * LDN;
            #pragma unroll
            for (int l = 0; l < BS8; ++l) {
                rb[m][l][0] = *(const float4*)(bp + bsrc[l]);
                rb[m][l][1] = *(const float4*)(bp + bsrc[l] + 4);
            }
        }
    };
    auto sts = [&](int buf) {
        #pragma unroll
        for (int l = 0; l < AV; ++l)
            *(uint4*)(Asm + buf * ABYTES + adst[l]) = rah[l];
        #pragma unroll
        for (int m = 0; m < NMAT; ++m) {
            #pragma unroll
            for (int l = 0; l < BS8; ++l) {
                *(uint4*)(Bsm + (m * 2 + buf) * BBYTES + bdst[l]) = make_uint4(
                    f2h2(rb[m][l][0].x, rb[m][l][0].y), f2h2(rb[m][l][0].z, rb[m][l][0].w),
                    f2h2(rb[m][l][1].x, rb[m][l][1].y), f2h2(rb[m][l][1].z, rb[m][l][1].w));
            }
        }
    };

    fetch(0);
    sts(0);
    __syncthreads();

    #pragma unroll 1
    for (int c = 0; c < KT; ++c) {
        const int cur = c & 1;
        if (c + 1 < KT) fetch(c + 1);
        #pragma unroll
        for (int s = 0; s < 2; ++s) {
            uint32_t a[MI][4];
            #pragma unroll
            for (int mi = 0; mi < MI; ++mi)
                ldsm4(a[mi], aaddr0 + cur * ABYTES + mi * 16 * 80 + s * 32);
            #pragma unroll
            for (int m = 0; m < NMAT; ++m) {
                const uint32_t bb = bsb + (m * 2 + cur) * BBYTES + s * 2048;
                #pragma unroll
                for (int ni = 0; ni < NI; ++ni) {
                    uint32_t b0, b1;
                    ldsm2t(b0, b1, bb + bni[ni]);
                    #pragma unroll
                    for (int mi = 0; mi < MI; ++mi) mma_f16(acc[m][mi][ni], a[mi], b0, b1);
                }
            }
        }
        if (c + 1 < KT) sts((c + 1) & 1);
        __syncthreads();
    }

    // ---- epilogue ----
    #pragma unroll
    for (int mi = 0; mi < MI; ++mi) {
        #pragma unroll
        for (int h = 0; h < 2; ++h) {
            int rloc = wm0 + mi * 16 + lr + 8 * h;
            if constexpr (MODE == 0) {
                int row = m0 + rloc;
                #pragma unroll
                for (int ni = 0; ni < NI; ++ni) {
                    int col = n0 + wn0 + ni * 8 + lc * 2;
                    float g0 = acc[0][mi][ni][2 * h], g1 = acc[0][mi][ni][2 * h + 1];
                    float u0 = acc[1][mi][ni][2 * h], u1 = acc[1][mi][ni][2 * h + 1];
                    *(__half2*)&g_S[(size_t)row * SF_ + col] =
                        __floats2half2_rn(siluf(g0) * u0, siluf(g1) * u1);
                }
            } else if constexpr (MODE == 1) {
                int row = m0 + rloc;
                float gt = g_gate[row];
                #pragma unroll
                for (int ni = 0; ni < NI; ++ni) {
                    int col = n0 + wn0 + ni * 8 + lc * 2;
                    float2 o = make_float2(gt * acc[0][mi][ni][2 * h], gt * acc[0][mi][ni][2 * h + 1]);
                    *(float2*)&Out[(size_t)row * H_ + col] = o;
                }
            } else if constexpr (MODE == 2) {
                int rr = m0 + rloc;
                if (rr < cnt) {
                    size_t rp = (size_t)(pb + rr) * F_;
                    #pragma unroll
                    for (int ni = 0; ni < NI; ++ni) {
                        int col = n0 + wn0 + ni * 8 + lc * 2;
                        float g0 = acc[0][mi][ni][2 * h], g1 = acc[0][mi][ni][2 * h + 1];
                        float u0 = acc[1][mi][ni][2 * h], u1 = acc[1][mi][ni][2 * h + 1];
                        *(__half2*)&g_Hbuf[rp + col] =
                            __floats2half2_rn(siluf(g0) * u0, siluf(g1) * u1);
                    }
                }
            } else {
                int rr = m0 + rloc;
                if (rr < cnt) {
                    int tk = g_tok[e * T_ + rr];
                    float w = g_wt[e * T_ + rr];
                    float* op = Out + (size_t)tk * H_;
                    #pragma unroll
                    for (int ni = 0; ni < NI; ++ni) {
                        int col = n0 + wn0 + ni * 8 + lc * 2;
                        atomicAdd(op + col,     w * acc[0][mi][ni][2 * h]);
                        atomicAdd(op + col + 1, w * acc[0][mi][ni][2 * h + 1]);
                    }
                }
            }
        }
    }
}

extern "C" void kernel_launch(void* const* d_in, const int* in_sizes, int n_in,
                              void* d_out, int out_size)
{
    const float* x   = (const float*)d_in[0];
    const float* rw  = (const float*)d_in[1];
    const float* wg  = (const float*)d_in[2];
    const float* wu  = (const float*)d_in[3];
    const float* wd  = (const float*)d_in[4];
    const float* shg = (const float*)d_in[5];
    const float* shu = (const float*)d_in[6];
    const float* shd = (const float*)d_in[7];
    const float* seg = (const float*)d_in[8];
    float* out = (float*)d_out;

    init_kernel<<<1, 64>>>();
    convx_kernel<<<(T_ * H_) / 2048, 256>>>(x);
    router_kernel<<<T_, 256>>>(x, rw, seg);
    scan_kernel<<<1, 32>>>();

    hgemm<128, 0><<<dim3(SF_ / 64, T_ / 128), 256>>>(shg, shu, nullptr);
    hgemm<128, 2><<<dim3(F_ / 64, T_ / 128, E_), 256>>>(wg, wu, nullptr);
    hgemm<32, 2><<<dim3(F_ / 64, 4, E_), 128>>>(wg, wu, nullptr);

    hgemm<128, 1><<<dim3(H_ / 128, T_ / 128), 256>>>(shd, nullptr, out);
    hgemm<128, 3><<<dim3(H_ / 128, T_ / 128, E_), 256>>>(wd, nullptr, out);
    hgemm<32, 3><<<dim3(H_ / 128, 4, E_), 128>>>(wd, nullptr, out);
}

// round 7
// speedup vs baseline: 5.1565x; 1.0521x over previous
#include <cuda_runtime.h>
#include <cuda_fp16.h>
#include <math.h>
#include <stdint.h>

#define T_ 2048
#define H_ 2048
#define F_ 1408
#define E_ 60
#define TOPK_ 4
#define SF_ 5632

__device__ __half g_Xh[(size_t)T_ * H_];
__device__ __half g_S[(size_t)T_ * SF_];
__device__ __half g_Hbuf[(size_t)T_ * TOPK_ * F_];
__device__ int   g_cnt[E_];
__device__ int   g_base[E_];
__device__ int   g_tok[E_ * T_];
__device__ float g_wt[E_ * T_];
__device__ float g_gate[T_];

__device__ __forceinline__ float siluf(float v) { return v / (1.f + expf(-v)); }
__device__ __forceinline__ uint32_t f2h2(float x, float y) {
    __half2 h = __floats2half2_rn(x, y);
    return *(uint32_t*)&h;
}
__device__ __forceinline__ uint32_t smem_u32(const void* p) {
    uint32_t a; asm("{ .reg .u64 t; cvta.to.shared.u64 t, %1; cvt.u32.u64 %0, t; }" : "=r"(a) : "l"(p)); return a;
}
#define SWZ(x) ((x) ^ (((x) >> 3) & 0x70))
#define CP_A16(dst, src) asm volatile("cp.async.cg.shared.global [%0], [%1], 16;" :: "r"(dst), "l"(src))
#define CP_COMMIT()      asm volatile("cp.async.commit_group;" ::: "memory")
#define CP_WAIT0()       asm volatile("cp.async.wait_group 0;" ::: "memory")

__device__ __forceinline__ void ldsm4(uint32_t r[4], uint32_t a) {
    asm volatile("ldmatrix.sync.aligned.m8n8.x4.shared.b16 {%0,%1,%2,%3}, [%4];"
        : "=r"(r[0]), "=r"(r[1]), "=r"(r[2]), "=r"(r[3]) : "r"(a));
}
__device__ __forceinline__ void ldsm4t(uint32_t r[4], uint32_t a) {
    asm volatile("ldmatrix.sync.aligned.m8n8.x4.trans.shared.b16 {%0,%1,%2,%3}, [%4];"
        : "=r"(r[0]), "=r"(r[1]), "=r"(r[2]), "=r"(r[3]) : "r"(a));
}
__device__ __forceinline__ void mma_f16(float c[4], const uint32_t a[4], uint32_t b0, uint32_t b1) {
    asm volatile("mma.sync.aligned.m16n8k16.row.col.f32.f16.f16.f32 "
        "{%0,%1,%2,%3},{%4,%5,%6,%7},{%8,%9},{%0,%1,%2,%3};"
        : "+f"(c[0]), "+f"(c[1]), "+f"(c[2]), "+f"(c[3])
        : "r"(a[0]), "r"(a[1]), "r"(a[2]), "r"(a[3]), "r"(b0), "r"(b1));
}

__global__ void init_kernel() { if (threadIdx.x < E_) g_cnt[threadIdx.x] = 0; }

__global__ __launch_bounds__(64) void scan_kernel() {
    __shared__ int s[64];
    int i = threadIdx.x;
    int v = (i < E_) ? g_cnt[i] : 0;
    s[i] = v;
    __syncthreads();
    #pragma unroll
    for (int d = 1; d < 64; d <<= 1) {
        int t = (i >= d) ? s[i - d] : 0;
        __syncthreads();
        s[i] += t;
        __syncthreads();
    }
    if (i < E_) g_base[i] = s[i] - v;
}

__global__ __launch_bounds__(256) void convx_kernel(const float* __restrict__ X) {
    size_t i = ((size_t)blockIdx.x * 256 + threadIdx.x) * 8;
    float4 a = *(const float4*)(X + i);
    float4 b = *(const float4*)(X + i + 4);
    uint4 o = make_uint4(f2h2(a.x, a.y), f2h2(a.z, a.w), f2h2(b.x, b.y), f2h2(b.z, b.w));
    *(uint4*)&g_Xh[i] = o;
}

__global__ __launch_bounds__(256) void router_kernel(
    const float* __restrict__ X, const float* __restrict__ RW,
    const float* __restrict__ SEG)
{
    int t = blockIdx.x;
    __shared__ float xs[H_];
    __shared__ float part[64][4];
    __shared__ float logits[E_];
    __shared__ float red[256];
    int tid = threadIdx.x;
    for (int i = tid; i < H_; i += 256) xs[i] = X[(size_t)t * H_ + i];
    __syncthreads();
    int e = tid >> 2, q = tid & 3;
    if (e < E_) {
        float s = 0.f;
        int h0 = q * (H_ / 4);
        for (int h = h0; h < h0 + H_ / 4; ++h) s += xs[h] * RW[(size_t)h * E_ + e];
        part[e][q] = s;
    }
    float gsum = 0.f;
    for (int i = tid; i < H_; i += 256) gsum += xs[i] * SEG[i];
    red[tid] = gsum;
    __syncthreads();
    if (e < E_ && q == 0) logits[e] = part[e][0] + part[e][1] + part[e][2] + part[e][3];
    for (int st = 128; st > 0; st >>= 1) {
        if (tid < st) red[tid] += red[tid + st];
        __syncthreads();
    }
    if (tid == 0) {
        g_gate[t] = 1.f / (1.f + expf(-red[0]));
        float mx = -1e30f;
        for (int i = 0; i < E_; ++i) mx = fmaxf(mx, logits[i]);
        float sum = 0.f;
        for (int i = 0; i < E_; ++i) { logits[i] = expf(logits[i] - mx); sum += logits[i]; }
        float inv = 1.f / sum;
        for (int k = 0; k < TOPK_; ++k) {
            int bi = 0; float bv = -1.f;
            for (int i = 0; i < E_; ++i) if (logits[i] > bv) { bv = logits[i]; bi = i; }
            logits[bi] = -1.f;
            int slot = atomicAdd(&g_cnt[bi], 1);
            g_tok[bi * T_ + slot] = t;
            g_wt[bi * T_ + slot]  = bv * inv;
        }
    }
}

// FP16 tensor-core grouped GEMM, BK=32, double-buffered, A via cp.async.
// MODE 0: g_S    = silu(Xh@B0)*(Xh@B1)      (dual, BN=64)
// MODE 1: Out    = gate*(g_S@B0)            (single, BN=128)
// MODE 2: g_Hbuf = silu(Xh[g]@B0e)*(Xh[g]@B1e)
// MODE 3: Out[tok] += w*(g_Hbuf@B0e)
template<int BM, int MODE>
__global__ __launch_bounds__((BM == 128) ? 256 : 128, 2) void hgemm(
    const float* __restrict__ B0, const float* __restrict__ B1,
    float* __restrict__ Out)
{
    constexpr int THREADS = (BM == 128) ? 256 : 128;
    constexpr int K    = (MODE == 1) ? SF_ : ((MODE == 3) ? F_ : H_);
    constexpr int LDN  = (MODE == 0) ? SF_ : ((MODE == 2) ? F_ : H_);
    constexpr bool DUAL = (MODE == 0) || (MODE == 2);
    constexpr int NMAT = DUAL ? 2 : 1;
    constexpr int BN   = DUAL ? 64 : 128;
    constexpr int NW   = THREADS / 32;
    constexpr int WC   = (BM == 128 && DUAL) ? 2 : 4;
    constexpr int WR   = NW / WC;
    constexpr int WM   = BM / WR;
    constexpr int WN   = BN / WC;
    constexpr int MI   = WM / 16, NI = WN / 8, NI2 = NI / 2;
    constexpr int KT   = K / 32;
    constexpr int ABYTES = BM * 80;
    constexpr int BBYTES = (BN / 64) * 4096;
    constexpr int AV   = BM * 4 / THREADS;
    constexpr int BS8  = 32 * (BN / 8) / THREADS;

    __shared__ __align__(16) char Asm[2 * ABYTES];
    __shared__ __align__(16) char Bsm[NMAT * 2 * BBYTES];
    __shared__ int toks[BM];

    const int tid = threadIdx.x, lane = tid & 31, warp = tid >> 5;
    const int lr = lane >> 2, lc = lane & 3;
    const int wm0 = (warp / WC) * WM, wn0 = (warp % WC) * WN;
    const int n0 = blockIdx.x * BN;

    int e = 0, cnt = 0, pb = 0, m0;
    if constexpr (MODE >= 2) {
        e = blockIdx.z; cnt = g_cnt[e]; pb = g_base[e];
        if constexpr (BM == 128) { m0 = blockIdx.y * 128; if (m0 + 128 > cnt) return; }
        else                     { m0 = (cnt & ~127) + blockIdx.y * 32; if (m0 >= cnt) return; }
    } else m0 = blockIdx.y * BM;

    const float* Bp0 = B0;
    const float* Bp1 = DUAL ? B1 : B0;
    if constexpr (MODE >= 2) {
        size_t off = (size_t)e * K * LDN;
        Bp0 += off; Bp1 += off;
    }
    if constexpr (MODE == 2) {
        if (tid < BM) { int mm = m0 + tid; toks[tid] = g_tok[e * T_ + (mm < cnt ? mm : cnt - 1)]; }
        __syncthreads();
    }

    // ---- loader assignments ----
    const __half* asrc[AV]; uint32_t adst[AV];
    const uint32_t asb = smem_u32(Asm), bsb = smem_u32(Bsm);
    #pragma unroll
    for (int l = 0; l < AV; ++l) {
        int idx = tid + l * THREADS;
        int row = idx >> 2, kq = idx & 3;
        const __half* base;
        if constexpr (MODE == 0)      base = g_Xh + (size_t)(m0 + row) * H_;
        else if constexpr (MODE == 1) base = g_S + (size_t)(m0 + row) * SF_;
        else if constexpr (MODE == 2) base = g_Xh + (size_t)toks[row] * H_;
        else { int rr = m0 + row; base = g_Hbuf + (size_t)(pb + (rr < cnt ? rr : cnt - 1)) * F_; }
        asrc[l] = base + kq * 8;
        adst[l] = asb + (uint32_t)(row * 80 + kq * 16);
    }
    size_t bsrc[BS8]; int bdst[BS8];
    #pragma unroll
    for (int l = 0; l < BS8; ++l) {
        int idx = tid + l * THREADS;
        int k = idx / (BN / 8), n = (idx % (BN / 8)) * 8;
        bsrc[l] = (size_t)k * LDN + n0 + n;
        bdst[l] = (n >> 6) * 4096 + SWZ(k * 128 + (n & 63) * 2);
    }

    // ---- fragment addresses ----
    const uint32_t aaddr0 = asb + (uint32_t)((wm0 + (lane & 15)) * 80 + (lane >> 4) * 16);
    uint32_t bni2[NI2];
    #pragma unroll
    for (int pi = 0; pi < NI2; ++pi) {
        int col = wn0 + pi * 16 + (lane >> 4) * 8;
        bni2[pi] = (uint32_t)((col >> 6) * 4096 + SWZ((lane & 15) * 128 + (col & 63) * 2));
    }

    float acc[NMAT][MI][NI][4];
    #pragma unroll
    for (int m = 0; m < NMAT; ++m)
        #pragma unroll
        for (int mi = 0; mi < MI; ++mi)
            #pragma unroll
            for (int ni = 0; ni < NI; ++ni)
                #pragma unroll
                for (int j = 0; j < 4; ++j) acc[m][mi][ni][j] = 0.f;

    uint2 rbh[NMAT][BS8][2];

    auto fetchB = [&](int c) {
        #pragma unroll
        for (int m = 0; m < NMAT; ++m) {
            const float* bp = (m == 0 ? Bp0 : Bp1) + (size_t)c * 32 * LDN;
            #pragma unroll
            for (int l = 0; l < BS8; ++l) {
                float4 v0 = *(const float4*)(bp + bsrc[l]);
                float4 v1 = *(const float4*)(bp + bsrc[l] + 4);
                rbh[m][l][0] = make_uint2(f2h2(v0.x, v0.y), f2h2(v0.z, v0.w));
                rbh[m][l][1] = make_uint2(f2h2(v1.x, v1.y), f2h2(v1.z, v1.w));
            }
        }
    };
    auto stsB = [&](int buf) {
        #pragma unroll
        for (int m = 0; m < NMAT; ++m)
            #pragma unroll
            for (int l = 0; l < BS8; ++l)
                *(uint4*)(Bsm + (m * 2 + buf) * BBYTES + bdst[l]) = make_uint4(
                    rbh[m][l][0].x, rbh[m][l][0].y, rbh[m][l][1].x, rbh[m][l][1].y);
    };
    auto cpA = [&](int c, int buf) {
        #pragma unroll
        for (int l = 0; l < AV; ++l)
            CP_A16(adst[l] + buf * ABYTES, asrc[l] + c * 32);
        CP_COMMIT();
    };

    cpA(0, 0);
    fetchB(0);
    stsB(0);
    CP_WAIT0();
    __syncthreads();

    #pragma unroll 1
    for (int c = 0; c < KT; ++c) {
        const int cur = c & 1;
        if (c + 1 < KT) {
            cpA(c + 1, cur ^ 1);
            fetchB(c + 1);
        }
        #pragma unroll
        for (int s = 0; s < 2; ++s) {
            uint32_t a[MI][4];
            #pragma unroll
            for (int mi = 0; mi < MI; ++mi)
                ldsm4(a[mi], aaddr0 + cur * ABYTES + mi * 16 * 80 + s * 32);
            #pragma unroll
            for (int m = 0; m < NMAT; ++m) {
                const uint32_t bb = bsb + (m * 2 + cur) * BBYTES + s * 2048;
                #pragma unroll
                for (int pi = 0; pi < NI2; ++pi) {
                    uint32_t b[4];
                    ldsm4t(b, bb + bni2[pi]);
                    #pragma unroll
                    for (int mi = 0; mi < MI; ++mi) {
                        mma_f16(acc[m][mi][2 * pi],     a[mi], b[0], b[1]);
                        mma_f16(acc[m][mi][2 * pi + 1], a[mi], b[2], b[3]);
                    }
                }
            }
        }
        if (c + 1 < KT) stsB(cur ^ 1);
        CP_WAIT0();
        __syncthreads();
    }

    // ---- epilogue ----
    #pragma unroll
    for (int mi = 0; mi < MI; ++mi) {
        #pragma unroll
        for (int h = 0; h < 2; ++h) {
            int rloc = wm0 + mi * 16 + lr + 8 * h;
            if constexpr (MODE == 0) {
                int row = m0 + rloc;
                #pragma unroll
                for (int ni = 0; ni < NI; ++ni) {
                    int col = n0 + wn0 + ni * 8 + lc * 2;
                    float g0 = acc[0][mi][ni][2 * h], g1 = acc[0][mi][ni][2 * h + 1];
                    float u0 = acc[1][mi][ni][2 * h], u1 = acc[1][mi][ni][2 * h + 1];
                    *(__half2*)&g_S[(size_t)row * SF_ + col] =
                        __floats2half2_rn(siluf(g0) * u0, siluf(g1) * u1);
                }
            } else if constexpr (MODE == 1) {
                int row = m0 + rloc;
                float gt = g_gate[row];
                #pragma unroll
                for (int ni = 0; ni < NI; ++ni) {
                    int col = n0 + wn0 + ni * 8 + lc * 2;
                    float2 o = make_float2(gt * acc[0][mi][ni][2 * h], gt * acc[0][mi][ni][2 * h + 1]);
                    *(float2*)&Out[(size_t)row * H_ + col] = o;
                }
            } else if constexpr (MODE == 2) {
                int rr = m0 + rloc;
                if (rr < cnt) {
                    size_t rp = (size_t)(pb + rr) * F_;
                    #pragma unroll
                    for (int ni = 0; ni < NI; ++ni) {
                        int col = n0 + wn0 + ni * 8 + lc * 2;
                        float g0 = acc[0][mi][ni][2 * h], g1 = acc[0][mi][ni][2 * h + 1];
                        float u0 = acc[1][mi][ni][2 * h], u1 = acc[1][mi][ni][2 * h + 1];
                        *(__half2*)&g_Hbuf[rp + col] =
                            __floats2half2_rn(siluf(g0) * u0, siluf(g1) * u1);
                    }
                }
            } else {
                int rr = m0 + rloc;
                if (rr < cnt) {
                    int tk = g_tok[e * T_ + rr];
                    float w = g_wt[e * T_ + rr];
                    float* op = Out + (size_t)tk * H_;
                    #pragma unroll
                    for (int ni = 0; ni < NI; ++ni) {
                        int col = n0 + wn0 + ni * 8 + lc * 2;
                        atomicAdd(op + col,     w * acc[0][mi][ni][2 * h]);
                        atomicAdd(op + col + 1, w * acc[0][mi][ni][2 * h + 1]);
                    }
                }
            }
        }
    }
}

extern "C" void kernel_launch(void* const* d_in, const int* in_sizes, int n_in,
                              void* d_out, int out_size)
{
    const float* x   = (const float*)d_in[0];
    const float* rw  = (const float*)d_in[1];
    const float* wg  = (const float*)d_in[2];
    const float* wu  = (const float*)d_in[3];
    const float* wd  = (const float*)d_in[4];
    const float* shg = (const float*)d_in[5];
    const float* shu = (const float*)d_in[6];
    const float* shd = (const float*)d_in[7];
    const float* seg = (const float*)d_in[8];
    float* out = (float*)d_out;

    init_kernel<<<1, 64>>>();
    convx_kernel<<<(T_ * H_) / 2048, 256>>>(x);
    router_kernel<<<T_, 256>>>(x, rw, seg);
    scan_kernel<<<1, 64>>>();

    hgemm<128, 0><<<dim3(SF_ / 64, T_ / 128), 256>>>(shg, shu, nullptr);
    hgemm<128, 2><<<dim3(F_ / 64, T_ / 128, E_), 256>>>(wg, wu, nullptr);
    hgemm<32, 2><<<dim3(F_ / 64, 4, E_), 128>>>(wg, wu, nullptr);

    hgemm<128, 1><<<dim3(H_ / 128, T_ / 128), 256>>>(shd, nullptr, out);
    hgemm<128, 3><<<dim3(H_ / 128, T_ / 128, E_), 256>>>(wd, nullptr, out);
    hgemm<32, 3><<<dim3(H_ / 128, 4, E_), 128>>>(wd, nullptr, out);
}